// round 3
// baseline (speedup 1.0000x reference)
#include <cuda_runtime.h>
#include <math.h>

#define Bn 64
#define Hn 512
#define En 256
#define Vn 32000
#define Sn 64
#define NVB 500   /* Vn / 64 v-blocks in logits kernel */

// ---------------- persistent device state (no cudaMalloc allowed) ------------
__device__ float g_h[2][Bn * Hn];        // double-buffered hidden state
__device__ float g_c[Bn * Hn];           // cell state
__device__ float g_gates[4 * Hn * Bn];   // gate accumulator, layout [row][b]
__device__ float g_pval[Bn * NVB];       // argmax partials (value)
__device__ int   g_pidx[Bn * NVB];       // argmax partials (index)
__device__ int   g_tf[Sn];               // decoded use_tf flags

__device__ __forceinline__ float sigmoidf_(float x) {
    return 1.0f / (1.0f + expf(-x));
}

// ---- Blackwell packed fp32x2 helpers ----------------------------------------
__device__ __forceinline__ void up2(float& lo, float& hi, unsigned long long v) {
    asm("mov.b64 {%0, %1}, %2;" : "=f"(lo), "=f"(hi) : "l"(v));
}
__device__ __forceinline__ void ffma2(unsigned long long& acc,
                                      unsigned long long a,
                                      unsigned long long b) {
    asm("fma.rn.f32x2 %0, %1, %2, %0;" : "+l"(acc) : "l"(a), "l"(b));
}

// ---------------- init: decode use_tf layout, zero scratch + out[:,0,:] ------
__global__ void init_kernel(const unsigned char* tf_raw, float* out) {
    if (blockIdx.x == 0) {
        __shared__ int mode;  // 0 = 1-byte bool, 1 = 4-byte word
        if (threadIdx.x == 0) {
            int gt1 = 0, odd1 = 0;
            for (int i = 0; i < Sn; i++) {
                unsigned char v = tf_raw[i];
                if (v > 1) gt1 = 1;
                if (v == 1 && (i & 3)) odd1 = 1;
            }
            mode = gt1 ? 1 : (odd1 ? 0 : 1);
        }
        __syncthreads();
        if (threadIdx.x < Sn) {
            int t = threadIdx.x;
            int val;
            if (mode == 0) val = (tf_raw[t] != 0);
            else           val = (((const unsigned int*)tf_raw)[t] != 0u);
            g_tf[t] = val;
        }
    }
    for (int i = blockIdx.x * blockDim.x + threadIdx.x; i < 4 * Hn * Bn;
         i += gridDim.x * blockDim.x)
        g_gates[i] = 0.0f;
    for (int i = blockIdx.x * blockDim.x + threadIdx.x; i < Bn * Vn;
         i += gridDim.x * blockDim.x) {
        int b = i / Vn, v = i - b * Vn;
        out[(size_t)b * Sn * Vn + v] = 0.0f;
    }
}

// ---------------- gates: split-K GEMM with atomic accumulation ---------------
// grid (16 j-blocks, 6 k-slices) x 256 threads.
__global__ __launch_bounds__(256) void gates_kernel(
    int k, const int* __restrict__ captions, const float* __restrict__ emb,
    const float* __restrict__ W_ih, const float* __restrict__ W_hh,
    const float* __restrict__ enc)
{
    __shared__ float xh_s[32][68];   // [kk][b]
    __shared__ float w_s[32][132];   // [kk][row]
    __shared__ int   tok_s[Bn];

    int tid = threadIdx.x;
    int j0 = blockIdx.x * 32;
    int slice = blockIdx.y;
    bool xpart = (slice < 2);
    int kslice0 = xpart ? slice * 128 : (slice - 2) * 128;

    if (xpart) {
        if (k == 0) {
            if (tid < Bn) tok_s[tid] = captions[tid * Sn + 0];
        } else {
            int b = tid >> 2, l4 = tid & 3;
            float bv = -3.4e38f; int bi = 0x7fffffff;
            for (int p = l4; p < NVB; p += 4) {
                float v = g_pval[b * NVB + p];
                int  ii = g_pidx[b * NVB + p];
                if (v > bv || (v == bv && ii < bi)) { bv = v; bi = ii; }
            }
            #pragma unroll
            for (int off = 2; off > 0; off >>= 1) {
                float ov = __shfl_down_sync(0xffffffffu, bv, off, 4);
                int   oi = __shfl_down_sync(0xffffffffu, bi, off, 4);
                if (ov > bv || (ov == bv && oi < bi)) { bv = ov; bi = oi; }
            }
            if (l4 == 0)
                tok_s[b] = g_tf[k] ? captions[b * Sn + k] : bi;
        }
    }
    __syncthreads();

    float acc[4][8];
    #pragma unroll
    for (int g = 0; g < 4; g++)
        #pragma unroll
        for (int u = 0; u < 8; u++) acc[g][u] = 0.0f;

    int jj = tid & 31, bb = tid >> 5;

    for (int t8 = 0; t8 < 4; t8++) {
        int kb = t8 * 32;
        {
            int b = tid >> 2, kq = tid & 3;
            int kk0 = kq * 8;
            if (xpart) {
                int tok = tok_s[b];
                const float* row = emb + (size_t)tok * En;
                #pragma unroll
                for (int i = 0; i < 8; i++) {
                    int kg = kslice0 + kb + kk0 + i;
                    xh_s[kk0 + i][b] = (tok == 0) ? 0.0f : row[kg];
                }
            } else {
                const float* hsrc = (k == 0) ? (enc + b * Hn) : (&g_h[k & 1][b * Hn]);
                #pragma unroll
                for (int i = 0; i < 8; i++) {
                    int kg = kslice0 + kb + kk0 + i;
                    xh_s[kk0 + i][b] = hsrc[kg];
                }
            }
        }
        {
            int k4 = tid & 7, r0 = tid >> 3;
            #pragma unroll
            for (int pass = 0; pass < 4; pass++) {
                int r = r0 + pass * 32;
                int gate = r >> 5;
                int R = gate * Hn + j0 + (r & 31);
                int kg = kslice0 + kb + k4 * 4;
                const float* wptr = xpart ? (W_ih + (size_t)R * En + kg)
                                          : (W_hh + (size_t)R * Hn + kg);
                float4 w4 = *(const float4*)wptr;
                w_s[k4 * 4 + 0][r] = w4.x;
                w_s[k4 * 4 + 1][r] = w4.y;
                w_s[k4 * 4 + 2][r] = w4.z;
                w_s[k4 * 4 + 3][r] = w4.w;
            }
        }
        __syncthreads();
        #pragma unroll
        for (int kk = 0; kk < 32; kk++) {
            float w0 = w_s[kk][jj], w1 = w_s[kk][32 + jj];
            float w2 = w_s[kk][64 + jj], w3 = w_s[kk][96 + jj];
            float4 hA = *(const float4*)&xh_s[kk][bb * 8];
            float4 hB = *(const float4*)&xh_s[kk][bb * 8 + 4];
            float hv[8] = {hA.x, hA.y, hA.z, hA.w, hB.x, hB.y, hB.z, hB.w};
            #pragma unroll
            for (int u = 0; u < 8; u++) {
                acc[0][u] += w0 * hv[u];
                acc[1][u] += w1 * hv[u];
                acc[2][u] += w2 * hv[u];
                acc[3][u] += w3 * hv[u];
            }
        }
        __syncthreads();
    }

    #pragma unroll
    for (int g = 0; g < 4; g++) {
        int R = g * Hn + j0 + jj;
        #pragma unroll
        for (int u = 0; u < 8; u++)
            atomicAdd(&g_gates[R * Bn + bb * 8 + u], acc[g][u]);
    }
}

// ---------------- cell update; also re-zeros gate accumulator ----------------
__global__ __launch_bounds__(256) void cell_kernel(
    int k, const float* __restrict__ b_ih, const float* __restrict__ b_hh)
{
    int idx = blockIdx.x * 256 + threadIdx.x;
    int b = idx & 63;
    int j = idx >> 6;

    float gi = g_gates[(0 * Hn + j) * Bn + b] + b_ih[0 * Hn + j] + b_hh[0 * Hn + j];
    float gf = g_gates[(1 * Hn + j) * Bn + b] + b_ih[1 * Hn + j] + b_hh[1 * Hn + j];
    float gg = g_gates[(2 * Hn + j) * Bn + b] + b_ih[2 * Hn + j] + b_hh[2 * Hn + j];
    float go = g_gates[(3 * Hn + j) * Bn + b] + b_ih[3 * Hn + j] + b_hh[3 * Hn + j];

    float c_old = (k == 0) ? 0.0f : g_c[b * Hn + j];
    float c = sigmoidf_(gf) * c_old + sigmoidf_(gi) * tanhf(gg);
    float h = sigmoidf_(go) * tanhf(c);
    g_c[b * Hn + j] = c;
    g_h[(k + 1) & 1][b * Hn + j] = h;

    g_gates[(0 * Hn + j) * Bn + b] = 0.0f;
    g_gates[(1 * Hn + j) * Bn + b] = 0.0f;
    g_gates[(2 * Hn + j) * Bn + b] = 0.0f;
    g_gates[(3 * Hn + j) * Bn + b] = 0.0f;
}

// ---------------- logits GEMM + argmax partials ------------------------------
// grid 500 x 128 threads. Block tile 64v x 64b, thread tile 8v x 4b.
// h stored DUPLICATED in smem so FFMA2 broadcast pairs come free from LDS.128.
__global__ __launch_bounds__(128) void logits_kernel(
    int k, const float* __restrict__ fc_w, const float* __restrict__ fc_b,
    float* __restrict__ out)
{
    __shared__ float w_s[32][68];    // [kk][v]   (64 v + pad)
    __shared__ float h2_s[32][132];  // [kk][2b]  duplicated (128 + pad)
    int tid = threadIdx.x;
    int v0 = blockIdx.x * 64;
    int tv = tid & 7, tb = tid >> 3;           // 8 v-threads x 16 b-threads
    const float* hcur = g_h[(k + 1) & 1];

    unsigned long long acc2[4][4];  // [vpair][b]
    #pragma unroll
    for (int i = 0; i < 4; i++)
        #pragma unroll
        for (int j = 0; j < 4; j++) acc2[i][j] = 0ull;

    for (int t8 = 0; t8 < 16; t8++) {
        int kb = t8 * 32;
        // fill W tile: 64 v x 32 k (2048 floats / 128 threads = 4 x float4)
        {
            int k4 = tid & 7, vv = tid >> 3;   // k4: 8 groups of 4k, vv: 16
            #pragma unroll
            for (int pass = 0; pass < 4; pass++) {
                int v = vv + pass * 16;
                float4 w4 = *(const float4*)(fc_w + (size_t)(v0 + v) * Hn + kb + k4 * 4);
                w_s[k4 * 4 + 0][v] = w4.x;
                w_s[k4 * 4 + 1][v] = w4.y;
                w_s[k4 * 4 + 2][v] = w4.z;
                w_s[k4 * 4 + 3][v] = w4.w;
            }
        }
        // fill duplicated h tile: 64 b x 32 k, each value written twice
        {
            int b = tid >> 1, half = tid & 1;   // one b per 2 threads, 16 k each
            const float* hb = hcur + b * Hn + kb + half * 16;
            #pragma unroll
            for (int q = 0; q < 4; q++) {
                float4 a = *(const float4*)(hb + q * 4);
                int kk0 = half * 16 + q * 4;
                *(float2*)&h2_s[kk0 + 0][2 * b] = make_float2(a.x, a.x);
                *(float2*)&h2_s[kk0 + 1][2 * b] = make_float2(a.y, a.y);
                *(float2*)&h2_s[kk0 + 2][2 * b] = make_float2(a.z, a.z);
                *(float2*)&h2_s[kk0 + 3][2 * b] = make_float2(a.w, a.w);
            }
        }
        __syncthreads();
        #pragma unroll
        for (int kk = 0; kk < 32; kk++) {
            ulonglong2 wA = *(const ulonglong2*)&w_s[kk][tv * 8];
            ulonglong2 wB = *(const ulonglong2*)&w_s[kk][tv * 8 + 4];
            unsigned long long wd[4] = {wA.x, wA.y, wB.x, wB.y};
            ulonglong2 hA = *(const ulonglong2*)&h2_s[kk][tb * 8];      // b, b+1 dup
            ulonglong2 hB = *(const ulonglong2*)&h2_s[kk][tb * 8 + 4];  // b+2, b+3 dup
            unsigned long long hd[4] = {hA.x, hA.y, hB.x, hB.y};
            #pragma unroll
            for (int i = 0; i < 4; i++)
                #pragma unroll
                for (int j = 0; j < 4; j++)
                    ffma2(acc2[i][j], wd[i], hd[j]);
        }
        __syncthreads();
    }

    int t = k + 1;
    float bias[8];
    #pragma unroll
    for (int i = 0; i < 8; i++) bias[i] = fc_b[v0 + tv * 8 + i];

    #pragma unroll
    for (int j = 0; j < 4; j++) {
        int b = tb * 4 + j;
        float vals[8];
        #pragma unroll
        for (int i = 0; i < 4; i++) {
            float lo, hi;
            up2(lo, hi, acc2[i][j]);
            vals[2 * i]     = lo + bias[2 * i];
            vals[2 * i + 1] = hi + bias[2 * i + 1];
        }

        float4 r0 = make_float4(vals[0], vals[1], vals[2], vals[3]);
        float4 r1 = make_float4(vals[4], vals[5], vals[6], vals[7]);
        float* obase = out + ((size_t)b * Sn + t) * Vn + v0 + tv * 8;
        *(float4*)obase = r0;
        *(float4*)(obase + 4) = r1;

        // per-b argmax partial over this block's 64 v (lowest index on ties)
        float bv = vals[0]; int bi = v0 + tv * 8;
        #pragma unroll
        for (int i = 1; i < 8; i++) {
            int vi = v0 + tv * 8 + i;
            if (vals[i] > bv) { bv = vals[i]; bi = vi; }
        }
        #pragma unroll
        for (int off = 4; off > 0; off >>= 1) {
            float ov = __shfl_down_sync(0xffffffffu, bv, off, 8);
            int   oi = __shfl_down_sync(0xffffffffu, bi, off, 8);
            if (ov > bv || (ov == bv && oi < bi)) { bv = ov; bi = oi; }
        }
        if (tv == 0) {
            g_pval[b * NVB + blockIdx.x] = bv;
            g_pidx[b * NVB + blockIdx.x] = bi;
        }
    }
}

// ---------------- launch ------------------------------------------------------
extern "C" void kernel_launch(void* const* d_in, const int* in_sizes, int n_in,
                              void* d_out, int out_size) {
    (void)in_sizes; (void)n_in; (void)out_size;
    const float*         enc  = (const float*)d_in[0];
    const int*           caps = (const int*)d_in[1];
    const unsigned char* tf   = (const unsigned char*)d_in[2];
    const float*         emb  = (const float*)d_in[3];
    const float*         W_ih = (const float*)d_in[4];
    const float*         W_hh = (const float*)d_in[5];
    const float*         b_ih = (const float*)d_in[6];
    const float*         b_hh = (const float*)d_in[7];
    const float*         fc_w = (const float*)d_in[8];
    const float*         fc_b = (const float*)d_in[9];
    float* out = (float*)d_out;

    init_kernel<<<512, 256>>>(tf, out);
    dim3 gGrid(16, 6);
    for (int k = 0; k < 63; k++) {
        gates_kernel<<<gGrid, 256>>>(k, caps, emb, W_ih, W_hh, enc);
        cell_kernel<<<128, 256>>>(k, b_ih, b_hh);
        logits_kernel<<<500, 128>>>(k, fc_w, fc_b, out);
    }
}

// round 4
// speedup vs baseline: 1.1754x; 1.1754x over previous
#include <cuda_runtime.h>
#include <math.h>

#define Bn 64
#define Hn 512
#define En 256
#define Vn 32000
#define Sn 64
#define NVB 1000  /* Vn / 32 v-blocks in logits kernel */

// ---------------- persistent device state (no cudaMalloc allowed) ------------
__device__ float g_h[2][Bn * Hn];        // double-buffered hidden state
__device__ float g_c[Bn * Hn];           // cell state
__device__ float g_gates[4 * Hn * Bn];   // gate accumulator, layout [row][b]
__device__ float g_pval[Bn * NVB];       // argmax partials (value)
__device__ int   g_pidx[Bn * NVB];       // argmax partials (index)
__device__ int   g_tf[Sn];               // decoded use_tf flags

__device__ __forceinline__ float sigmoidf_(float x) {
    return 1.0f / (1.0f + expf(-x));
}

// ---------------- init: decode use_tf layout, zero scratch + out[:,0,:] ------
__global__ void init_kernel(const unsigned char* tf_raw, float* out) {
    if (blockIdx.x == 0) {
        __shared__ int mode;  // 0 = 1-byte bool, 1 = 4-byte word
        if (threadIdx.x == 0) {
            int gt1 = 0, odd1 = 0;
            for (int i = 0; i < Sn; i++) {
                unsigned char v = tf_raw[i];
                if (v > 1) gt1 = 1;
                if (v == 1 && (i & 3)) odd1 = 1;
            }
            mode = gt1 ? 1 : (odd1 ? 0 : 1);
        }
        __syncthreads();
        if (threadIdx.x < Sn) {
            int t = threadIdx.x;
            int val;
            if (mode == 0) val = (tf_raw[t] != 0);
            else           val = (((const unsigned int*)tf_raw)[t] != 0u);
            g_tf[t] = val;
        }
    }
    for (int i = blockIdx.x * blockDim.x + threadIdx.x; i < 4 * Hn * Bn;
         i += gridDim.x * blockDim.x)
        g_gates[i] = 0.0f;
    for (int i = blockIdx.x * blockDim.x + threadIdx.x; i < Bn * Vn;
         i += gridDim.x * blockDim.x) {
        int b = i / Vn, v = i - b * Vn;
        out[(size_t)b * Sn * Vn + v] = 0.0f;
    }
}

// ---------------- gates: split-K GEMM with atomic accumulation ---------------
// grid (16 j-blocks, 6 k-slices) x 256 threads.
__global__ __launch_bounds__(256) void gates_kernel(
    int k, const int* __restrict__ captions, const float* __restrict__ emb,
    const float* __restrict__ W_ih, const float* __restrict__ W_hh,
    const float* __restrict__ enc)
{
    __shared__ float xh_s[32][68];   // [kk][b]
    __shared__ float w_s[32][132];   // [kk][row]
    __shared__ int   tok_s[Bn];

    int tid = threadIdx.x;
    int j0 = blockIdx.x * 32;
    int slice = blockIdx.y;
    bool xpart = (slice < 2);
    int kslice0 = xpart ? slice * 128 : (slice - 2) * 128;

    if (xpart) {
        if (k == 0) {
            if (tid < Bn) tok_s[tid] = captions[tid * Sn + 0];
        } else {
            int b = tid >> 2, l4 = tid & 3;
            float bv = -3.4e38f; int bi = 0x7fffffff;
            for (int p = l4; p < NVB; p += 4) {
                float v = g_pval[b * NVB + p];
                int  ii = g_pidx[b * NVB + p];
                if (v > bv || (v == bv && ii < bi)) { bv = v; bi = ii; }
            }
            #pragma unroll
            for (int off = 2; off > 0; off >>= 1) {
                float ov = __shfl_down_sync(0xffffffffu, bv, off, 4);
                int   oi = __shfl_down_sync(0xffffffffu, bi, off, 4);
                if (ov > bv || (ov == bv && oi < bi)) { bv = ov; bi = oi; }
            }
            if (l4 == 0)
                tok_s[b] = g_tf[k] ? captions[b * Sn + k] : bi;
        }
    }
    __syncthreads();

    float acc[4][8];
    #pragma unroll
    for (int g = 0; g < 4; g++)
        #pragma unroll
        for (int u = 0; u < 8; u++) acc[g][u] = 0.0f;

    int jj = tid & 31, bb = tid >> 5;

    for (int t8 = 0; t8 < 4; t8++) {
        int kb = t8 * 32;
        {
            int b = tid >> 2, kq = tid & 3;
            int kk0 = kq * 8;
            if (xpart) {
                int tok = tok_s[b];
                const float* row = emb + (size_t)tok * En;
                #pragma unroll
                for (int i = 0; i < 8; i++) {
                    int kg = kslice0 + kb + kk0 + i;
                    xh_s[kk0 + i][b] = (tok == 0) ? 0.0f : row[kg];
                }
            } else {
                const float* hsrc = (k == 0) ? (enc + b * Hn) : (&g_h[k & 1][b * Hn]);
                #pragma unroll
                for (int i = 0; i < 8; i++) {
                    int kg = kslice0 + kb + kk0 + i;
                    xh_s[kk0 + i][b] = hsrc[kg];
                }
            }
        }
        {
            int k4 = tid & 7, r0 = tid >> 3;
            #pragma unroll
            for (int pass = 0; pass < 4; pass++) {
                int r = r0 + pass * 32;
                int gate = r >> 5;
                int R = gate * Hn + j0 + (r & 31);
                int kg = kslice0 + kb + k4 * 4;
                const float* wptr = xpart ? (W_ih + (size_t)R * En + kg)
                                          : (W_hh + (size_t)R * Hn + kg);
                float4 w4 = *(const float4*)wptr;
                w_s[k4 * 4 + 0][r] = w4.x;
                w_s[k4 * 4 + 1][r] = w4.y;
                w_s[k4 * 4 + 2][r] = w4.z;
                w_s[k4 * 4 + 3][r] = w4.w;
            }
        }
        __syncthreads();
        #pragma unroll
        for (int kk = 0; kk < 32; kk++) {
            float w0 = w_s[kk][jj], w1 = w_s[kk][32 + jj];
            float w2 = w_s[kk][64 + jj], w3 = w_s[kk][96 + jj];
            float4 hA = *(const float4*)&xh_s[kk][bb * 8];
            float4 hB = *(const float4*)&xh_s[kk][bb * 8 + 4];
            float hv[8] = {hA.x, hA.y, hA.z, hA.w, hB.x, hB.y, hB.z, hB.w};
            #pragma unroll
            for (int u = 0; u < 8; u++) {
                acc[0][u] += w0 * hv[u];
                acc[1][u] += w1 * hv[u];
                acc[2][u] += w2 * hv[u];
                acc[3][u] += w3 * hv[u];
            }
        }
        __syncthreads();
    }

    #pragma unroll
    for (int g = 0; g < 4; g++) {
        int R = g * Hn + j0 + jj;
        #pragma unroll
        for (int u = 0; u < 8; u++)
            atomicAdd(&g_gates[R * Bn + bb * 8 + u], acc[g][u]);
    }
}

// ---------------- cell update; also re-zeros gate accumulator ----------------
__global__ __launch_bounds__(256) void cell_kernel(
    int k, const float* __restrict__ b_ih, const float* __restrict__ b_hh)
{
    int idx = blockIdx.x * 256 + threadIdx.x;
    int b = idx & 63;
    int j = idx >> 6;

    float gi = g_gates[(0 * Hn + j) * Bn + b] + b_ih[0 * Hn + j] + b_hh[0 * Hn + j];
    float gf = g_gates[(1 * Hn + j) * Bn + b] + b_ih[1 * Hn + j] + b_hh[1 * Hn + j];
    float gg = g_gates[(2 * Hn + j) * Bn + b] + b_ih[2 * Hn + j] + b_hh[2 * Hn + j];
    float go = g_gates[(3 * Hn + j) * Bn + b] + b_ih[3 * Hn + j] + b_hh[3 * Hn + j];

    float c_old = (k == 0) ? 0.0f : g_c[b * Hn + j];
    float c = sigmoidf_(gf) * c_old + sigmoidf_(gi) * tanhf(gg);
    float h = sigmoidf_(go) * tanhf(c);
    g_c[b * Hn + j] = c;
    g_h[(k + 1) & 1][b * Hn + j] = h;

    g_gates[(0 * Hn + j) * Bn + b] = 0.0f;
    g_gates[(1 * Hn + j) * Bn + b] = 0.0f;
    g_gates[(2 * Hn + j) * Bn + b] = 0.0f;
    g_gates[(3 * Hn + j) * Bn + b] = 0.0f;
}

// ---------------- logits GEMM + argmax partials ------------------------------
// grid 1000 x 128 threads. Block tile 32v x 64b, thread tile 4v x 4b.
__global__ __launch_bounds__(128) void logits_kernel(
    int k, const float* __restrict__ fc_w, const float* __restrict__ fc_b,
    float* __restrict__ out)
{
    __shared__ float w_s[32][36];  // [kk][v]  (32 v + pad)
    __shared__ float h_s[32][68];  // [kk][b]
    int tid = threadIdx.x;
    int v0 = blockIdx.x * 32;
    int tv = tid & 7, tb = tid >> 3;   // 8 v-threads x 16 b-threads
    const float* hcur = g_h[(k + 1) & 1];

    float acc[4][4];
    #pragma unroll
    for (int i = 0; i < 4; i++)
        #pragma unroll
        for (int j = 0; j < 4; j++) acc[i][j] = 0.0f;

    for (int t8 = 0; t8 < 16; t8++) {
        int kb = t8 * 32;
        // fill W tile: 32 v x 32 k (1024 floats / 128 threads = 2 x float4)
        {
            int k4 = tid & 7, vv0 = tid >> 3;  // 8 k-groups x 16 v
            #pragma unroll
            for (int pass = 0; pass < 2; pass++) {
                int vv = vv0 + pass * 16;
                float4 w4 = *(const float4*)(fc_w + (size_t)(v0 + vv) * Hn + kb + k4 * 4);
                w_s[k4 * 4 + 0][vv] = w4.x;
                w_s[k4 * 4 + 1][vv] = w4.y;
                w_s[k4 * 4 + 2][vv] = w4.z;
                w_s[k4 * 4 + 3][vv] = w4.w;
            }
        }
        // fill h tile: 64 b x 32 k (2048 floats / 128 threads = 4 x float4)
        {
            int b = tid >> 1, kq = tid & 1;   // 2 k-halves of 16
            const float* hb = hcur + b * Hn + kb + kq * 16;
            #pragma unroll
            for (int q = 0; q < 4; q++) {
                float4 a = *(const float4*)(hb + q * 4);
                int kk0 = kq * 16 + q * 4;
                h_s[kk0 + 0][b] = a.x;
                h_s[kk0 + 1][b] = a.y;
                h_s[kk0 + 2][b] = a.z;
                h_s[kk0 + 3][b] = a.w;
            }
        }
        __syncthreads();
        #pragma unroll
        for (int kk = 0; kk < 32; kk++) {
            float4 w = *(const float4*)&w_s[kk][tv * 4];
            float4 h = *(const float4*)&h_s[kk][tb * 4];
            float wv[4] = {w.x, w.y, w.z, w.w};
            float hv[4] = {h.x, h.y, h.z, h.w};
            #pragma unroll
            for (int i = 0; i < 4; i++)
                #pragma unroll
                for (int j = 0; j < 4; j++)
                    acc[i][j] += wv[i] * hv[j];
        }
        __syncthreads();
    }

    int t = k + 1;
    float bias[4];
    #pragma unroll
    for (int i = 0; i < 4; i++) bias[i] = fc_b[v0 + tv * 4 + i];

    #pragma unroll
    for (int j = 0; j < 4; j++) {
        int b = tb * 4 + j;
        float vals[4];
        #pragma unroll
        for (int i = 0; i < 4; i++) vals[i] = acc[i][j] + bias[i];

        float4 r = make_float4(vals[0], vals[1], vals[2], vals[3]);
        *(float4*)(out + ((size_t)b * Sn + t) * Vn + v0 + tv * 4) = r;

        // per-b argmax partial over this block's 32 v (lowest index on ties)
        float bv = vals[0]; int bi = v0 + tv * 4;
        #pragma unroll
        for (int i = 1; i < 4; i++)
            if (vals[i] > bv) { bv = vals[i]; bi = v0 + tv * 4 + i; }
        #pragma unroll
        for (int off = 4; off > 0; off >>= 1) {
            float ov = __shfl_down_sync(0xffffffffu, bv, off, 8);
            int   oi = __shfl_down_sync(0xffffffffu, bi, off, 8);
            if (ov > bv || (ov == bv && oi < bi)) { bv = ov; bi = oi; }
        }
        if (tv == 0) {
            g_pval[b * NVB + blockIdx.x] = bv;
            g_pidx[b * NVB + blockIdx.x] = bi;
        }
    }
}

// ---------------- launch ------------------------------------------------------
extern "C" void kernel_launch(void* const* d_in, const int* in_sizes, int n_in,
                              void* d_out, int out_size) {
    (void)in_sizes; (void)n_in; (void)out_size;
    const float*         enc  = (const float*)d_in[0];
    const int*           caps = (const int*)d_in[1];
    const unsigned char* tf   = (const unsigned char*)d_in[2];
    const float*         emb  = (const float*)d_in[3];
    const float*         W_ih = (const float*)d_in[4];
    const float*         W_hh = (const float*)d_in[5];
    const float*         b_ih = (const float*)d_in[6];
    const float*         b_hh = (const float*)d_in[7];
    const float*         fc_w = (const float*)d_in[8];
    const float*         fc_b = (const float*)d_in[9];
    float* out = (float*)d_out;

    init_kernel<<<512, 256>>>(tf, out);
    dim3 gGrid(16, 6);
    for (int k = 0; k < 63; k++) {
        gates_kernel<<<gGrid, 256>>>(k, caps, emb, W_ih, W_hh, enc);
        cell_kernel<<<128, 256>>>(k, b_ih, b_hh);
        logits_kernel<<<1000, 128>>>(k, fc_w, fc_b, out);
    }
}

// round 6
// speedup vs baseline: 2.4140x; 2.0538x over previous
#include <cuda_runtime.h>
#include <cuda_bf16.h>
#include <math.h>
#include <stdint.h>

#define Bn 64
#define Hn 512
#define En 256
#define Vn 32000
#define Sn 64
#define NVB 250       /* Vn / 128 v-blocks in logits kernel */
#define NKT 32        /* k-tiles of 16 (Hn/16) */

// ---------------- persistent device state (no cudaMalloc allowed) ------------
__device__ float g_h[2][Bn * Hn];
__device__ float g_c[Bn * Hn];
__device__ float g_gates[4 * Hn * Bn];
__device__ float g_pval[Bn * NVB];
__device__ int   g_pidx[Bn * NVB];
__device__ int   g_tf[Sn];

// W in mma-A-fragment order: [mtile][ktile][lane][8 bf16]  (2000*32 tiles)
__device__ __nv_bfloat16 g_wfrag_hi[(size_t)Vn * Hn];
__device__ __nv_bfloat16 g_wfrag_lo[(size_t)Vn * Hn];
// h in mma-B-fragment order: [ntile][ktile][lane][4 bf16]  (8*32 tiles)
__device__ __nv_bfloat16 g_hfrag_hi[Bn * Hn];
__device__ __nv_bfloat16 g_hfrag_lo[Bn * Hn];

__device__ __forceinline__ float sigmoidf_(float x) {
    return 1.0f / (1.0f + expf(-x));
}

__device__ __forceinline__ void mma16816(float* c, const uint4& a, const uint2& b) {
    asm volatile(
        "mma.sync.aligned.m16n8k16.row.col.f32.bf16.bf16.f32 "
        "{%0,%1,%2,%3}, {%4,%5,%6,%7}, {%8,%9}, {%0,%1,%2,%3};"
        : "+f"(c[0]), "+f"(c[1]), "+f"(c[2]), "+f"(c[3])
        : "r"(a.x), "r"(a.y), "r"(a.z), "r"(a.w), "r"(b.x), "r"(b.y));
}

// ---------------- one-time W conversion to fragment-ordered bf16 hi/lo -------
__global__ void convert_w_kernel(const float* __restrict__ fc_w) {
    size_t idx = (size_t)blockIdx.x * blockDim.x + threadIdx.x;
    if (idx >= (size_t)Vn * Hn) return;
    int v = (int)(idx >> 9);       // Hn = 512
    int kg = (int)(idx & 511);
    float w = fc_w[idx];
    __nv_bfloat16 hi = __float2bfloat16(w);
    __nv_bfloat16 lo = __float2bfloat16(w - __bfloat162float(hi));
    int mtile = v >> 4, r = v & 15;
    int ktile = kg >> 4, c = kg & 15;
    int lane = (r & 7) * 4 + ((c & 7) >> 1);
    int reg  = (r >> 3) + 2 * (c >> 3);
    int pos  = c & 1;
    size_t off = ((size_t)(mtile * NKT + ktile) * 32 + lane) * 8 + reg * 2 + pos;
    g_wfrag_hi[off] = hi;
    g_wfrag_lo[off] = lo;
}

// ---------------- init: decode use_tf layout, zero scratch + out[:,0,:] ------
__global__ void init_kernel(const unsigned char* tf_raw, float* out) {
    if (blockIdx.x == 0) {
        __shared__ int mode;
        if (threadIdx.x == 0) {
            int gt1 = 0, odd1 = 0;
            for (int i = 0; i < Sn; i++) {
                unsigned char v = tf_raw[i];
                if (v > 1) gt1 = 1;
                if (v == 1 && (i & 3)) odd1 = 1;
            }
            mode = gt1 ? 1 : (odd1 ? 0 : 1);
        }
        __syncthreads();
        if (threadIdx.x < Sn) {
            int t = threadIdx.x;
            int val;
            if (mode == 0) val = (tf_raw[t] != 0);
            else           val = (((const unsigned int*)tf_raw)[t] != 0u);
            g_tf[t] = val;
        }
    }
    for (int i = blockIdx.x * blockDim.x + threadIdx.x; i < 4 * Hn * Bn;
         i += gridDim.x * blockDim.x)
        g_gates[i] = 0.0f;
    for (int i = blockIdx.x * blockDim.x + threadIdx.x; i < Bn * Vn;
         i += gridDim.x * blockDim.x) {
        int b = i / Vn, v = i - b * Vn;
        out[(size_t)b * Sn * Vn + v] = 0.0f;
    }
}

// ---------------- gates: split-K GEMM with atomic accumulation ---------------
__global__ __launch_bounds__(256) void gates_kernel(
    int k, const int* __restrict__ captions, const float* __restrict__ emb,
    const float* __restrict__ W_ih, const float* __restrict__ W_hh,
    const float* __restrict__ enc)
{
    __shared__ float xh_s[32][68];
    __shared__ float w_s[32][132];
    __shared__ int   tok_s[Bn];

    int tid = threadIdx.x;
    int j0 = blockIdx.x * 32;
    int slice = blockIdx.y;
    bool xpart = (slice < 2);
    int kslice0 = xpart ? slice * 128 : (slice - 2) * 128;

    if (xpart) {
        if (k == 0) {
            if (tid < Bn) tok_s[tid] = captions[tid * Sn + 0];
        } else {
            int b = tid >> 2, l4 = tid & 3;
            float bv = -3.4e38f; int bi = 0x7fffffff;
            for (int p = l4; p < NVB; p += 4) {
                float v = g_pval[b * NVB + p];
                int  ii = g_pidx[b * NVB + p];
                if (v > bv || (v == bv && ii < bi)) { bv = v; bi = ii; }
            }
            #pragma unroll
            for (int off = 2; off > 0; off >>= 1) {
                float ov = __shfl_down_sync(0xffffffffu, bv, off, 4);
                int   oi = __shfl_down_sync(0xffffffffu, bi, off, 4);
                if (ov > bv || (ov == bv && oi < bi)) { bv = ov; bi = oi; }
            }
            if (l4 == 0)
                tok_s[b] = g_tf[k] ? captions[b * Sn + k] : bi;
        }
    }
    __syncthreads();

    float acc[4][8];
    #pragma unroll
    for (int g = 0; g < 4; g++)
        #pragma unroll
        for (int u = 0; u < 8; u++) acc[g][u] = 0.0f;

    int jj = tid & 31, bb = tid >> 5;

    for (int t8 = 0; t8 < 4; t8++) {
        int kb = t8 * 32;
        {
            int b = tid >> 2, kq = tid & 3;
            int kk0 = kq * 8;
            if (xpart) {
                int tok = tok_s[b];
                const float* row = emb + (size_t)tok * En;
                #pragma unroll
                for (int i = 0; i < 8; i++) {
                    int kg = kslice0 + kb + kk0 + i;
                    xh_s[kk0 + i][b] = (tok == 0) ? 0.0f : row[kg];
                }
            } else {
                const float* hsrc = (k == 0) ? (enc + b * Hn) : (&g_h[k & 1][b * Hn]);
                #pragma unroll
                for (int i = 0; i < 8; i++) {
                    int kg = kslice0 + kb + kk0 + i;
                    xh_s[kk0 + i][b] = hsrc[kg];
                }
            }
        }
        {
            int k4 = tid & 7, r0 = tid >> 3;
            #pragma unroll
            for (int pass = 0; pass < 4; pass++) {
                int r = r0 + pass * 32;
                int gate = r >> 5;
                int R = gate * Hn + j0 + (r & 31);
                int kg = kslice0 + kb + k4 * 4;
                const float* wptr = xpart ? (W_ih + (size_t)R * En + kg)
                                          : (W_hh + (size_t)R * Hn + kg);
                float4 w4 = *(const float4*)wptr;
                w_s[k4 * 4 + 0][r] = w4.x;
                w_s[k4 * 4 + 1][r] = w4.y;
                w_s[k4 * 4 + 2][r] = w4.z;
                w_s[k4 * 4 + 3][r] = w4.w;
            }
        }
        __syncthreads();
        #pragma unroll
        for (int kk = 0; kk < 32; kk++) {
            float w0 = w_s[kk][jj], w1 = w_s[kk][32 + jj];
            float w2 = w_s[kk][64 + jj], w3 = w_s[kk][96 + jj];
            float4 hA = *(const float4*)&xh_s[kk][bb * 8];
            float4 hB = *(const float4*)&xh_s[kk][bb * 8 + 4];
            float hv[8] = {hA.x, hA.y, hA.z, hA.w, hB.x, hB.y, hB.z, hB.w};
            #pragma unroll
            for (int u = 0; u < 8; u++) {
                acc[0][u] += w0 * hv[u];
                acc[1][u] += w1 * hv[u];
                acc[2][u] += w2 * hv[u];
                acc[3][u] += w3 * hv[u];
            }
        }
        __syncthreads();
    }

    #pragma unroll
    for (int g = 0; g < 4; g++) {
        int R = g * Hn + j0 + jj;
        #pragma unroll
        for (int u = 0; u < 8; u++)
            atomicAdd(&g_gates[R * Bn + bb * 8 + u], acc[g][u]);
    }
}

// ---------------- cell update; re-zeros gates; emits fragment-ordered h ------
__global__ __launch_bounds__(256) void cell_kernel(
    int k, const float* __restrict__ b_ih, const float* __restrict__ b_hh)
{
    int idx = blockIdx.x * 256 + threadIdx.x;
    int b = idx & 63;
    int j = idx >> 6;

    float gi = g_gates[(0 * Hn + j) * Bn + b] + b_ih[0 * Hn + j] + b_hh[0 * Hn + j];
    float gf = g_gates[(1 * Hn + j) * Bn + b] + b_ih[1 * Hn + j] + b_hh[1 * Hn + j];
    float gg = g_gates[(2 * Hn + j) * Bn + b] + b_ih[2 * Hn + j] + b_hh[2 * Hn + j];
    float go = g_gates[(3 * Hn + j) * Bn + b] + b_ih[3 * Hn + j] + b_hh[3 * Hn + j];

    float c_old = (k == 0) ? 0.0f : g_c[b * Hn + j];
    float c = sigmoidf_(gf) * c_old + sigmoidf_(gi) * tanhf(gg);
    float h = sigmoidf_(go) * tanhf(c);
    g_c[b * Hn + j] = c;
    g_h[(k + 1) & 1][b * Hn + j] = h;

    g_gates[(0 * Hn + j) * Bn + b] = 0.0f;
    g_gates[(1 * Hn + j) * Bn + b] = 0.0f;
    g_gates[(2 * Hn + j) * Bn + b] = 0.0f;
    g_gates[(3 * Hn + j) * Bn + b] = 0.0f;

    // fragment-ordered bf16 hi/lo for the logits MMA (B operand)
    __nv_bfloat16 hi = __float2bfloat16(h);
    __nv_bfloat16 lo = __float2bfloat16(h - __bfloat162float(hi));
    int ntile = b >> 3, n = b & 7;
    int ktile = j >> 4, c2 = j & 15;
    int lane = n * 4 + ((c2 & 7) >> 1);
    int reg  = c2 >> 3;
    int pos  = c2 & 1;
    uint32_t off = ((uint32_t)(ntile * NKT + ktile) * 32 + lane) * 4 + reg * 2 + pos;
    g_hfrag_hi[off] = hi;
    g_hfrag_lo[off] = lo;
}

// ---------------- logits GEMM via mma.sync bf16 (3-term split) ---------------
// grid 250 x 256 threads (8 warps). Block tile 128v x 64b.
// warp (mw=wid&3, nw=wid>>2): mtiles mw*2..+1 (32v), ntiles nw*4..+3 (32b).
__global__ __launch_bounds__(256) void logits_mma_kernel(
    int k, const float* __restrict__ fc_b, float* __restrict__ out)
{
    __shared__ float s_out[Bn][132];   // [b][v] for coalesced store + argmax

    int tid = threadIdx.x;
    int wid = tid >> 5, lane = tid & 31;
    int mw = wid & 3, nw = wid >> 2;
    int gid = lane >> 2, tig = lane & 3;

    const uint4* wh4 = (const uint4*)g_wfrag_hi;
    const uint4* wl4 = (const uint4*)g_wfrag_lo;
    const uint2* hh2 = (const uint2*)g_hfrag_hi;
    const uint2* hl2 = (const uint2*)g_hfrag_lo;

    int mt_g0 = blockIdx.x * 8 + mw * 2;   // global mtile base for this warp

    float acc[2][4][4];
    #pragma unroll
    for (int mt = 0; mt < 2; mt++)
        #pragma unroll
        for (int nt = 0; nt < 4; nt++)
            #pragma unroll
            for (int i = 0; i < 4; i++) acc[mt][nt][i] = 0.0f;

    for (int kt = 0; kt < NKT; kt++) {
        uint4 ahi[2], alo[2];
        #pragma unroll
        for (int mt = 0; mt < 2; mt++) {
            size_t base = ((size_t)(mt_g0 + mt) * NKT + kt) * 32 + lane;
            ahi[mt] = wh4[base];
            alo[mt] = wl4[base];
        }
        #pragma unroll
        for (int nt = 0; nt < 4; nt++) {
            int nt_g = nw * 4 + nt;
            uint32_t bbase = (uint32_t)(nt_g * NKT + kt) * 32 + lane;
            uint2 bhi = hh2[bbase];
            uint2 blo = hl2[bbase];
            #pragma unroll
            for (int mt = 0; mt < 2; mt++) {
                mma16816(acc[mt][nt], ahi[mt], bhi);
                mma16816(acc[mt][nt], ahi[mt], blo);
                mma16816(acc[mt][nt], alo[mt], bhi);
            }
        }
    }

    // write accumulators to smem transpose buffer: s_out[b][v]
    #pragma unroll
    for (int mt = 0; mt < 2; mt++) {
        int vl = mw * 32 + mt * 16 + gid;
        #pragma unroll
        for (int nt = 0; nt < 4; nt++) {
            int bl = (nw * 4 + nt) * 8 + tig * 2;
            s_out[bl][vl]         = acc[mt][nt][0];
            s_out[bl + 1][vl]     = acc[mt][nt][1];
            s_out[bl][vl + 8]     = acc[mt][nt][2];
            s_out[bl + 1][vl + 8] = acc[mt][nt][3];
        }
    }
    __syncthreads();

    // epilogue: bias + coalesced store + argmax partials
    int v0g = blockIdx.x * 128;
    int t = k + 1;
    int b = tid >> 2, q = tid & 3;
    float* orow = out + ((size_t)b * Sn + t) * Vn + v0g + q * 32;
    float bv = -3.4e38f; int bi = 0x7fffffff;
    #pragma unroll
    for (int g8 = 0; g8 < 8; g8++) {
        float4 r;
        float* sp = &s_out[b][q * 32 + g8 * 4];
        const float* bp = fc_b + v0g + q * 32 + g8 * 4;
        r.x = sp[0] + bp[0];
        r.y = sp[1] + bp[1];
        r.z = sp[2] + bp[2];
        r.w = sp[3] + bp[3];
        *(float4*)(orow + g8 * 4) = r;
        int vb = v0g + q * 32 + g8 * 4;
        if (r.x > bv) { bv = r.x; bi = vb; }
        if (r.y > bv) { bv = r.y; bi = vb + 1; }
        if (r.z > bv) { bv = r.z; bi = vb + 2; }
        if (r.w > bv) { bv = r.w; bi = vb + 3; }
    }
    #pragma unroll
    for (int off = 2; off > 0; off >>= 1) {
        float ov = __shfl_down_sync(0xffffffffu, bv, off, 4);
        int   oi = __shfl_down_sync(0xffffffffu, bi, off, 4);
        if (ov > bv || (ov == bv && oi < bi)) { bv = ov; bi = oi; }
    }
    if (q == 0) {
        g_pval[b * NVB + blockIdx.x] = bv;
        g_pidx[b * NVB + blockIdx.x] = bi;
    }
}

// ---------------- launch ------------------------------------------------------
extern "C" void kernel_launch(void* const* d_in, const int* in_sizes, int n_in,
                              void* d_out, int out_size) {
    (void)in_sizes; (void)n_in; (void)out_size;
    const float*         enc  = (const float*)d_in[0];
    const int*           caps = (const int*)d_in[1];
    const unsigned char* tf   = (const unsigned char*)d_in[2];
    const float*         emb  = (const float*)d_in[3];
    const float*         W_ih = (const float*)d_in[4];
    const float*         W_hh = (const float*)d_in[5];
    const float*         b_ih = (const float*)d_in[6];
    const float*         b_hh = (const float*)d_in[7];
    const float*         fc_w = (const float*)d_in[8];
    const float*         fc_b = (const float*)d_in[9];
    float* out = (float*)d_out;

    init_kernel<<<512, 256>>>(tf, out);
    convert_w_kernel<<<(Vn * Hn + 255) / 256, 256>>>(fc_w);
    dim3 gGrid(16, 6);
    for (int k = 0; k < 63; k++) {
        gates_kernel<<<gGrid, 256>>>(k, caps, emb, W_ih, W_hh, enc);
        cell_kernel<<<128, 256>>>(k, b_ih, b_hh);
        logits_mma_kernel<<<250, 256>>>(k, fc_b, out);
    }
}